// round 16
// baseline (speedup 1.0000x reference)
#include <cuda_runtime.h>
#include <cuda_bf16.h>
#include <math.h>
#include <stdint.h>

#define NCUT 200000
#define GOI  500
#define BB   512
#define LL   16
#define CC   224
#define GTOT 20000
#define LOG2PI 1.8378770664093453
#define JPB 64
#define LWP 232   // padded tf32 lw row stride
#define OSTR 116  // staging row stride (uints)

// ---------------- device scratch (zero at load; k_B last block restores) ---
__device__ unsigned short g_d[(size_t)BB * GOI * CC];  // bf16 deltas
__device__ float4 g_spl[GOI * CC];
__device__ float  g_S[BB];
__device__ double g_acc[2];
__device__ unsigned g_done;

// ---------------- helpers ----------------
__device__ __forceinline__ int iminmax(int v, int hi) { v = v < 0 ? 0 : v; return v > hi ? hi : v; }
__device__ __forceinline__ float blo(unsigned u) { return __int_as_float(u << 16); }
__device__ __forceinline__ float bhi(unsigned u) { return __int_as_float(u & 0xffff0000u); }
__device__ __forceinline__ float dsc(const unsigned short* dr, int i) {
    return __int_as_float(((unsigned)__ldg(&dr[i])) << 16);
}
__device__ __forceinline__ unsigned bfpack2(float a, float b) {
    __nv_bfloat162 h2 = __floats2bfloat162_rn(a, b);
    return *reinterpret_cast<unsigned*>(&h2);
}
__device__ __forceinline__ uint32_t f2tf32(float f) {
    uint32_t r; asm("cvt.rna.tf32.f32 %0, %1;" : "=r"(r) : "f"(f)); return r;
}
__device__ __forceinline__ void mma_tf32(float& d0, float& d1, float& d2, float& d3,
                                         uint32_t a0, uint32_t a1, uint32_t a2, uint32_t a3,
                                         uint32_t b0, uint32_t b1) {
    asm("mma.sync.aligned.m16n8k8.row.col.f32.tf32.tf32.f32 "
        "{%0,%1,%2,%3}, {%4,%5,%6,%7}, {%8,%9}, {%0,%1,%2,%3};"
        : "+f"(d0), "+f"(d1), "+f"(d2), "+f"(d3)
        : "r"(a0), "r"(a1), "r"(a2), "r"(a3), "r"(b0), "r"(b1));
}

// ======== K1: pergene [0,G) + S [G, G+4*SB) ========
__global__ void __launch_bounds__(128) k_preS(const int* __restrict__ genes_oi,
                                              const float* __restrict__ logit_weight,
                                              const float* __restrict__ rho_weight,
                                              const float* __restrict__ rho_bias,
                                              const float* __restrict__ uh,
                                              const float* __restrict__ uw,
                                              const float* __restrict__ clustering,
                                              int G, int GT) {
    __shared__ float s_red[128];
    __shared__ float s_w[128];
    __shared__ float s_scan[128];
    int bid = blockIdx.x, t = threadIdx.x;

    if (bid >= G) {
        // ---- S[b] partial: one (j-range, b-quarter) per block ----
        int idx = bid - G;
        int bp = idx & 3;
        int j0 = (idx >> 2) * JPB;
        int jmax = GT - j0; if (jmax > JPB) jmax = JPB;
        int b = bp * 128 + t;
        const float4* cp = (const float4*)(clustering + (size_t)b * LL);
        float4 c0 = __ldg(cp + 0), c1 = __ldg(cp + 1), c2 = __ldg(cp + 2), c3 = __ldg(cp + 3);
        float s = 0.f;
        for (int jj = 0; jj < jmax; jj++) {
            int j = j0 + jj;
            const float4* rw = (const float4*)(rho_weight + (size_t)j * LL);
            float4 r0 = __ldg(rw + 0), r1 = __ldg(rw + 1), r2 = __ldg(rw + 2), r3 = __ldg(rw + 3);
            float z = 0.f;
            z = fmaf(c0.x, r0.x, z); z = fmaf(c0.y, r0.y, z); z = fmaf(c0.z, r0.z, z); z = fmaf(c0.w, r0.w, z);
            z = fmaf(c1.x, r1.x, z); z = fmaf(c1.y, r1.y, z); z = fmaf(c1.z, r1.z, z); z = fmaf(c1.w, r1.w, z);
            z = fmaf(c2.x, r2.x, z); z = fmaf(c2.y, r2.y, z); z = fmaf(c2.z, r2.z, z); z = fmaf(c2.w, r2.w, z);
            z = fmaf(c3.x, r3.x, z); z = fmaf(c3.y, r3.y, z); z = fmaf(c3.z, r3.z, z); z = fmaf(c3.w, r3.w, z);
            s = fmaf(__ldg(&rho_bias[j]), __expf(z), s);
        }
        atomicAdd(&g_S[b], s);
        return;
    }

    // ---- per-gene spline precompute + prior ----
    int g = bid;
    int gene = genes_oi[g];

    float psum = 0.f;
    const float* lwr = logit_weight + (size_t)gene * (LL * CC);
    for (int i = t; i < LL * CC; i += 128) {
        float v = lwr[i];
        psum -= 0.5f * v * v;
    }
    if (t < LL) { float v = rho_weight[gene * LL + t]; psum -= 0.5f * v * v; }

    const int nh_t[3] = {128, 64, 32};
    const int oh_t[3] = {0, 128, 192};
    const int ow_t[3] = {0, 127, 190};
    const float* uhr = uh + (size_t)gene * CC;
    const float* uwr = uw + (size_t)gene * 221;

    for (int s = 0; s < 3; s++) {
        int nh = nh_t[s], nw = nh - 1, oh = oh_t[s], ow = ow_t[s];
        float uwv = (t < nw) ? uwr[ow + t] : -1e30f;
        s_red[t] = uwv; __syncthreads();
        for (int o = 64; o; o >>= 1) { if (t < o) s_red[t] = fmaxf(s_red[t], s_red[t + o]); __syncthreads(); }
        float mx = s_red[0]; __syncthreads();
        float e = (t < nw) ? __expf(uwv - mx) : 0.f;
        s_red[t] = e; __syncthreads();
        for (int o = 64; o; o >>= 1) { if (t < o) s_red[t] += s_red[t + o]; __syncthreads(); }
        float inv = 1.0f / s_red[0]; __syncthreads();
        float w = e * inv;
        s_w[t] = w;
        s_scan[t] = w;
        __syncthreads();
        for (int o = 1; o < 128; o <<= 1) {
            float v = (t >= o) ? s_scan[t - o] : 0.f;
            __syncthreads();
            s_scan[t] += v;
            __syncthreads();
        }
        if (t < nh) {
            float loc = (t == 0) ? 0.f : ((t == nw) ? 1.0f : s_scan[t - 1]);
            float wl = (t >= 1) ? s_w[t - 1] : 0.f;
            float wr = (t <= nw - 1) ? w : 0.f;
            float wwv = 0.5f * (wl + wr);
            float wst = (t < nw) ? w : 0.f;
            int pos;
            if (s == 0)      pos = (t & 15) * 8 + (t >> 4);
            else if (s == 1) pos = 128 + (t & 7) * 8 + (t >> 3);
            else             pos = 192 + (t & 3) * 8 + (t >> 2);
            g_spl[g * CC + pos] = make_float4(uhr[oh + t], wwv, loc, wst);
        }
        __syncthreads();
    }

    s_red[t] = psum; __syncthreads();
    for (int o = 64; o; o >>= 1) { if (t < o) s_red[t] += s_red[t + o]; __syncthreads(); }
    if (t == 0) atomicAdd(&g_acc[1], (double)s_red[0]);
}

// ======== K2: delta GEMM tf32 + smem-staged stores ========
__global__ void __launch_bounds__(128) k_gemm(const int* __restrict__ genes_oi,
                                              const float* __restrict__ logit_weight,
                                              const float* __restrict__ clustering,
                                              int G) {
    __shared__ uint32_t s_lw[LL * LWP];
    __shared__ uint32_t s_out[4][16 * OSTR];
    int g = blockIdx.x, bs = blockIdx.y, t = threadIdx.x;
    int gene = __ldg(&genes_oi[g]);

    const float* lwr = logit_weight + (size_t)gene * (LL * CC);
    for (int i = t; i < LL * CC; i += 128) {
        int row = i / CC, col = i - row * CC;
        s_lw[row * LWP + col] = f2tf32(lwr[i]);
    }
    __syncthreads();

    int wid = t >> 5, lane = t & 31;
    int r = lane >> 2, k4 = lane & 3;
    uint32_t* sbuf = s_out[wid];

    for (int bt = 0; bt < 4; bt++) {
        int tilebase = (bs * 16 + wid * 4 + bt) * 16;
        int brow0 = tilebase + r;
        const float* cl0 = clustering + (size_t)brow0 * LL;
        const float* cl1 = cl0 + 8 * LL;
        uint32_t A0[4], A1[4];
        A0[0] = f2tf32(__ldg(cl0 + k4));      A0[1] = f2tf32(__ldg(cl1 + k4));
        A0[2] = f2tf32(__ldg(cl0 + k4 + 4));  A0[3] = f2tf32(__ldg(cl1 + k4 + 4));
        A1[0] = f2tf32(__ldg(cl0 + k4 + 8));  A1[1] = f2tf32(__ldg(cl1 + k4 + 8));
        A1[2] = f2tf32(__ldg(cl0 + k4 + 12)); A1[3] = f2tf32(__ldg(cl1 + k4 + 12));

#pragma unroll 4
        for (int ct = 0; ct < 28; ct++) {
            int col = (ct << 3) + r;
            uint32_t b00 = s_lw[k4 * LWP + col];
            uint32_t b01 = s_lw[(k4 + 4) * LWP + col];
            uint32_t b10 = s_lw[(k4 + 8) * LWP + col];
            uint32_t b11 = s_lw[(k4 + 12) * LWP + col];
            float d0 = 0.f, d1 = 0.f, d2 = 0.f, d3 = 0.f;
            mma_tf32(d0, d1, d2, d3, A0[0], A0[1], A0[2], A0[3], b00, b01);
            mma_tf32(d0, d1, d2, d3, A1[0], A1[1], A1[2], A1[3], b10, b11);
            sbuf[r * OSTR + (ct << 2) + k4]       = bfpack2(d0, d1);
            sbuf[(r + 8) * OSTR + (ct << 2) + k4] = bfpack2(d2, d3);
        }
        __syncwarp();
        for (int idx = lane; idx < 448; idx += 32) {
            int row = idx / 28, c4 = idx - row * 28;
            uint4 v = *(uint4*)&sbuf[row * OSTR + (c4 << 2)];
            *(uint4*)(g_d + ((size_t)(tilebase + row) * G + g) * CC + (c4 << 3)) = v;
        }
        __syncwarp();
    }
}

// ======== K3: main [0,MB) + rho [MB, MB+RB) + last-block finalize ========
__global__ void __launch_bounds__(128) k_B(const float* __restrict__ coord,
                                           const int* __restrict__ lgi,
                                           const int* __restrict__ lci,
                                           const int* __restrict__ lcgi,
                                           const float* __restrict__ clustering,
                                           const float* __restrict__ rho_weight,
                                           const float* __restrict__ rho_bias,
                                           float* __restrict__ out,
                                           int n, int GT, int MB, int G, float logGT) {
    __shared__ double s_acc[4];
    __shared__ double sd_[128];
    __shared__ int s_last;
    const unsigned FULL = 0xffffffffu;
    int bidx = blockIdx.x, t = threadIdx.x;

    if (bidx >= MB) {
        // ---------------- rho term per cut ----------------
        int i = (bidx - MB) * 128 + t;
        float v = 0.f;
        if (i < n) {
            int li = __ldg(&lcgi[i]);
            int row = li / GT;
            int j = li - row * GT;
            const float4* cp = (const float4*)(clustering + (size_t)row * LL);
            const float4* rw = (const float4*)(rho_weight + (size_t)j * LL);
            float4 c0 = __ldg(cp + 0), c1 = __ldg(cp + 1), c2 = __ldg(cp + 2), c3 = __ldg(cp + 3);
            float4 r0 = __ldg(rw + 0), r1 = __ldg(rw + 1), r2 = __ldg(rw + 2), r3 = __ldg(rw + 3);
            float z = 0.f;
            z = fmaf(c0.x, r0.x, z); z = fmaf(c0.y, r0.y, z); z = fmaf(c0.z, r0.z, z); z = fmaf(c0.w, r0.w, z);
            z = fmaf(c1.x, r1.x, z); z = fmaf(c1.y, r1.y, z); z = fmaf(c1.z, r1.z, z); z = fmaf(c1.w, r1.w, z);
            z = fmaf(c2.x, r2.x, z); z = fmaf(c2.y, r2.y, z); z = fmaf(c2.z, r2.z, z); z = fmaf(c2.w, r2.w, z);
            z = fmaf(c3.x, r3.x, z); z = fmaf(c3.y, r3.y, z); z = fmaf(c3.z, r3.z, z); z = fmaf(c3.w, r3.w, z);
            v = __logf(__ldg(&rho_bias[j])) + z - __logf(__ldg(&g_S[row]));
        }
        sd_[t] = (double)v;
        __syncthreads();
        for (int o = 64; o; o >>= 1) {
            if (t < o) sd_[t] += sd_[t + o];
            __syncthreads();
        }
        if (t == 0) atomicAdd(&g_acc[0], sd_[0]);
    } else {
        // ---------------- main per-cut spline ----------------
        int wid = t >> 5, lane = t & 31;
        int q = lane >> 3, ll = lane & 7;

        int cut = bidx * 16 + wid * 4 + q;
        bool live = cut < n;
        int cu = live ? cut : (n - 1);

        float x = __ldg(&coord[cu]);
        int gl = __ldg(&lgi[cu]);
        int ci = __ldg(&lci[cu]);

        const float4* splg = g_spl + (size_t)gl * CC;
        const unsigned short* drs = g_d + (size_t)ci * CC;
        const uint4* drow4 = (const uint4*)drs;
        float lad = 0.f;

        // ===== step 1 =====
        {
            uint4 u0 = __ldg(&drow4[ll * 2]);
            uint4 u1 = __ldg(&drow4[ll * 2 + 1]);
            unsigned wds[8] = {u0.x, u0.y, u0.z, u0.w, u1.x, u1.y, u1.z, u1.w};
            float dreg[16];
#pragma unroll
            for (int p = 0; p < 8; p++) { dreg[2 * p] = blo(wds[p]); dreg[2 * p + 1] = bhi(wds[p]); }
            float h[16], w[16];
            float area = 0.f; int cnt = 0;
#pragma unroll
            for (int j = 0; j < 16; j++) {
                float4 pj = __ldg(splg + (j << 3) + ll);
                float hv = __expf(pj.x + dreg[j]);
                h[j] = hv; w[j] = pj.w;
                cnt += (x >= pj.z) ? 1 : 0;
                area = fmaf(hv, pj.y, area);
            }
            cnt += __shfl_xor_sync(FULL, cnt, 1, 8);
            cnt += __shfl_xor_sync(FULL, cnt, 2, 8);
            cnt += __shfl_xor_sync(FULL, cnt, 4, 8);
            int bin = iminmax(cnt - 1, 126);
            float wprev = __shfl_up_sync(FULL, w[15], 1, 8);
            float cdf = 0.f;
            int ib = ll << 4;
            float wim1 = wprev;
#pragma unroll
            for (int j = 0; j < 16; j++) {
                int i = ib + j;
                float ct = ((i < bin) ? 0.5f * w[j] : 0.f) + ((i >= 1 && i <= bin) ? 0.5f * wim1 : 0.f);
                cdf = fmaf(h[j], ct, cdf);
                wim1 = w[j];
            }
            area += __shfl_xor_sync(FULL, area, 4, 8);
            cdf  += __shfl_xor_sync(FULL, cdf, 4, 8);
            float v = (lane & 4) ? cdf : area;
            v += __shfl_xor_sync(FULL, v, 1, 8);
            v += __shfl_xor_sync(FULL, v, 2, 8);
            float o = __shfl_xor_sync(FULL, v, 4, 8);
            area = (lane & 4) ? o : v;
            cdf  = (lane & 4) ? v : o;

            int b1 = bin + 1;
            float4 spb  = __ldg(splg + ((bin & 15) << 3) + (bin >> 4));
            float4 spb1 = __ldg(splg + ((b1 & 15) << 3) + (b1 >> 4));
            float hl = __expf(spb.x + dsc(drs, bin));
            float hr = __expf(spb1.x + dsc(drs, b1));
            float inv = __fdividef(1.f, area);
            float alpha = __fdividef(x - spb.z, spb.w);
            float hln = hl * inv, hrn = hr * inv;
            x = (0.5f * (hrn - hln) * alpha + hln) * spb.w * alpha + cdf * inv;
            lad += __logf(fmaf(hrn - hln, alpha, hln));
        }

        // ===== step 2 =====
        {
            uint4 u0 = __ldg(&drow4[16 + ll]);
            unsigned wds[4] = {u0.x, u0.y, u0.z, u0.w};
            float dreg[8];
#pragma unroll
            for (int p = 0; p < 4; p++) { dreg[2 * p] = blo(wds[p]); dreg[2 * p + 1] = bhi(wds[p]); }
            float h[8], w[8];
            float area = 0.f; int cnt = 0;
#pragma unroll
            for (int j = 0; j < 8; j++) {
                float4 pj = __ldg(splg + 128 + (j << 3) + ll);
                float hv = __expf(pj.x + dreg[j]);
                h[j] = hv; w[j] = pj.w;
                cnt += (x >= pj.z) ? 1 : 0;
                area = fmaf(hv, pj.y, area);
            }
            cnt += __shfl_xor_sync(FULL, cnt, 1, 8);
            cnt += __shfl_xor_sync(FULL, cnt, 2, 8);
            cnt += __shfl_xor_sync(FULL, cnt, 4, 8);
            int bin = iminmax(cnt - 1, 62);
            float wprev = __shfl_up_sync(FULL, w[7], 1, 8);
            float cdf = 0.f;
            int ib = ll << 3;
            float wim1 = wprev;
#pragma unroll
            for (int j = 0; j < 8; j++) {
                int i = ib + j;
                float ct = ((i < bin) ? 0.5f * w[j] : 0.f) + ((i >= 1 && i <= bin) ? 0.5f * wim1 : 0.f);
                cdf = fmaf(h[j], ct, cdf);
                wim1 = w[j];
            }
            area += __shfl_xor_sync(FULL, area, 4, 8);
            cdf  += __shfl_xor_sync(FULL, cdf, 4, 8);
            float v = (lane & 4) ? cdf : area;
            v += __shfl_xor_sync(FULL, v, 1, 8);
            v += __shfl_xor_sync(FULL, v, 2, 8);
            float o = __shfl_xor_sync(FULL, v, 4, 8);
            area = (lane & 4) ? o : v;
            cdf  = (lane & 4) ? v : o;

            int b1 = bin + 1;
            float4 spb  = __ldg(splg + 128 + ((bin & 7) << 3) + (bin >> 3));
            float4 spb1 = __ldg(splg + 128 + ((b1 & 7) << 3) + (b1 >> 3));
            float hl = __expf(spb.x + dsc(drs, 128 + bin));
            float hr = __expf(spb1.x + dsc(drs, 128 + b1));
            float inv = __fdividef(1.f, area);
            float alpha = __fdividef(x - spb.z, spb.w);
            float hln = hl * inv, hrn = hr * inv;
            x = (0.5f * (hrn - hln) * alpha + hln) * spb.w * alpha + cdf * inv;
            lad += __logf(fmaf(hrn - hln, alpha, hln));
        }

        // ===== step 3 =====
        {
            uint2 u0 = __ldg(&((const uint2*)drow4)[48 + ll]);
            float dreg[4] = {blo(u0.x), bhi(u0.x), blo(u0.y), bhi(u0.y)};
            float h[4], w[4];
            float area = 0.f; int cnt = 0;
#pragma unroll
            for (int j = 0; j < 4; j++) {
                float4 pj = __ldg(splg + 192 + (j << 3) + ll);
                float hv = __expf(pj.x + dreg[j]);
                h[j] = hv; w[j] = pj.w;
                cnt += (x >= pj.z) ? 1 : 0;
                area = fmaf(hv, pj.y, area);
            }
            cnt += __shfl_xor_sync(FULL, cnt, 1, 8);
            cnt += __shfl_xor_sync(FULL, cnt, 2, 8);
            cnt += __shfl_xor_sync(FULL, cnt, 4, 8);
            int bin = iminmax(cnt - 1, 30);
            float wprev = __shfl_up_sync(FULL, w[3], 1, 8);
            float cdf = 0.f;
            int ib = ll << 2;
            float wim1 = wprev;
#pragma unroll
            for (int j = 0; j < 4; j++) {
                int i = ib + j;
                float ct = ((i < bin) ? 0.5f * w[j] : 0.f) + ((i >= 1 && i <= bin) ? 0.5f * wim1 : 0.f);
                cdf = fmaf(h[j], ct, cdf);
                wim1 = w[j];
            }
            area += __shfl_xor_sync(FULL, area, 4, 8);
            cdf  += __shfl_xor_sync(FULL, cdf, 4, 8);
            float v = (lane & 4) ? cdf : area;
            v += __shfl_xor_sync(FULL, v, 1, 8);
            v += __shfl_xor_sync(FULL, v, 2, 8);
            float o = __shfl_xor_sync(FULL, v, 4, 8);
            area = (lane & 4) ? o : v;
            cdf  = (lane & 4) ? v : o;

            int b1 = bin + 1;
            float4 spb  = __ldg(splg + 192 + ((bin & 3) << 3) + (bin >> 2));
            float4 spb1 = __ldg(splg + 192 + ((b1 & 3) << 3) + (b1 >> 2));
            float hl = __expf(spb.x + dsc(drs, 192 + bin));
            float hr = __expf(spb1.x + dsc(drs, 192 + b1));
            float inv = __fdividef(1.f, area);
            float alpha = __fdividef(x - spb.z, spb.w);
            float hln = hl * inv, hrn = hr * inv;
            x = (0.5f * (hrn - hln) * alpha + hln) * spb.w * alpha + cdf * inv;
            lad += __logf(fmaf(hrn - hln, alpha, hln));
        }

        double acc = (live && ll == 0) ? (double)lad : 0.0;
        acc += __shfl_xor_sync(FULL, acc, 8);
        acc += __shfl_xor_sync(FULL, acc, 16);
        if (lane == 0) s_acc[wid] = acc;
        __syncthreads();
        if (t == 0) {
            double tt = s_acc[0] + s_acc[1] + s_acc[2] + s_acc[3];
            atomicAdd(&g_acc[0], tt);
        }
    }

    // ---------------- last-block finalize + state restore ----------------
    __threadfence();
    if (t == 0) {
        unsigned ticket = atomicAdd(&g_done, 1u);
        s_last = (ticket == gridDim.x - 1) ? 1 : 0;
    }
    __syncthreads();
    if (s_last) {
        if (t == 0) {
            double cnt = (double)G * (double)(LL * CC + LL);
            out[0] = (float)(-g_acc[0] - (double)n * (double)logGT
                             - g_acc[1] + 0.5 * LOG2PI * cnt);
            g_acc[0] = 0.0;
            g_acc[1] = 0.0;
            g_done = 0u;
        }
        for (int i = t; i < BB; i += 128) g_S[i] = 0.f;
    }
}

// ---------------- launch ----------------
extern "C" void kernel_launch(void* const* d_in, const int* in_sizes, int n_in,
                              void* d_out, int out_size) {
    const float* clustering    = (const float*)d_in[0];
    const float* coordinates   = (const float*)d_in[1];
    const int*   genes_oi      = (const int*)d_in[2];
    const int*   local_gene_ix = (const int*)d_in[3];
    const int*   lci           = (const int*)d_in[4];
    const int*   lcgi          = (const int*)d_in[5];
    const float* logit_weight  = (const float*)d_in[6];
    const float* rho_weight    = (const float*)d_in[7];
    const float* rho_bias      = (const float*)d_in[8];
    const float* uh            = (const float*)d_in[9];
    const float* uw            = (const float*)d_in[10];

    int N  = in_sizes[1];
    int G  = in_sizes[2];
    int B  = in_sizes[0] / LL;
    int GT = in_sizes[8];

    int SB = (GT + JPB - 1) / JPB;       // 313
    int MB = (N + 15) / 16;              // 12500
    int RB = (N + 127) / 128;            // 1563

    k_preS<<<G + 4 * SB, 128>>>(genes_oi, logit_weight, rho_weight, rho_bias,
                                uh, uw, clustering, G, GT);
    k_gemm<<<dim3(G, B / 256), 128>>>(genes_oi, logit_weight, clustering, G);
    k_B<<<MB + RB, 128>>>(coordinates, local_gene_ix, lci, lcgi,
                          clustering, rho_weight, rho_bias,
                          (float*)d_out, N, GT, MB, G, logf((float)GT));
}

// round 17
// speedup vs baseline: 1.0945x; 1.0945x over previous
#include <cuda_runtime.h>
#include <cuda_bf16.h>
#include <math.h>
#include <stdint.h>

#define NCUT 200000
#define GOI  500
#define BB   512
#define LL   16
#define CC   224
#define GTOT 20000
#define LOG2PI 1.8378770664093453
#define JPB 64
#define LWP 232   // padded tf32 lw row stride
#define OSTR 116  // staging row stride (uints)

// ---------------- device scratch (zero at load; k_final restores) ----------
__device__ unsigned short g_d[(size_t)BB * GOI * CC];  // bf16 deltas
__device__ float4 g_spl[GOI * CC];
__device__ float  g_S[BB];
__device__ double g_acc[2];

// ---------------- helpers ----------------
__device__ __forceinline__ int iminmax(int v, int hi) { v = v < 0 ? 0 : v; return v > hi ? hi : v; }
__device__ __forceinline__ float blo(unsigned u) { return __int_as_float(u << 16); }
__device__ __forceinline__ float bhi(unsigned u) { return __int_as_float(u & 0xffff0000u); }
__device__ __forceinline__ float dsc(const unsigned short* dr, int i) {
    return __int_as_float(((unsigned)__ldg(&dr[i])) << 16);
}
__device__ __forceinline__ unsigned bfpack2(float a, float b) {
    __nv_bfloat162 h2 = __floats2bfloat162_rn(a, b);
    return *reinterpret_cast<unsigned*>(&h2);
}
__device__ __forceinline__ uint32_t f2tf32(float f) {
    uint32_t r; asm("cvt.rna.tf32.f32 %0, %1;" : "=r"(r) : "f"(f)); return r;
}
__device__ __forceinline__ void mma_tf32(float& d0, float& d1, float& d2, float& d3,
                                         uint32_t a0, uint32_t a1, uint32_t a2, uint32_t a3,
                                         uint32_t b0, uint32_t b1) {
    asm("mma.sync.aligned.m16n8k8.row.col.f32.tf32.tf32.f32 "
        "{%0,%1,%2,%3}, {%4,%5,%6,%7}, {%8,%9}, {%0,%1,%2,%3};"
        : "+f"(d0), "+f"(d1), "+f"(d2), "+f"(d3)
        : "r"(a0), "r"(a1), "r"(a2), "r"(a3), "r"(b0), "r"(b1));
}

// ======== K1: pergene [0,G) + S [G, G+SB)  (R15 structure, warp scans) =====
__global__ void __launch_bounds__(128) k_preS(const int* __restrict__ genes_oi,
                                              const float* __restrict__ logit_weight,
                                              const float* __restrict__ rho_weight,
                                              const float* __restrict__ rho_bias,
                                              const float* __restrict__ uh,
                                              const float* __restrict__ uw,
                                              const float* __restrict__ clustering,
                                              int G, int GT) {
    __shared__ float s_m[4], s_s[4], s_c[4], s_wl[4];
    const unsigned FULL = 0xffffffffu;
    int bid = blockIdx.x, t = threadIdx.x;
    int wid = t >> 5, lane = t & 31;

    if (bid >= G) {
        // ---- S[b] partial: 128 threads cover 512 b in 4 passes (R15) ----
        int j0 = (bid - G) * JPB;
        int jmax = GT - j0; if (jmax > JPB) jmax = JPB;
        for (int bp = 0; bp < 4; bp++) {
            int b = bp * 128 + t;
            const float4* cp = (const float4*)(clustering + (size_t)b * LL);
            float4 c0 = __ldg(cp + 0), c1 = __ldg(cp + 1), c2 = __ldg(cp + 2), c3 = __ldg(cp + 3);
            float s = 0.f;
            for (int jj = 0; jj < jmax; jj++) {
                int j = j0 + jj;
                const float4* rw = (const float4*)(rho_weight + (size_t)j * LL);
                float4 r0 = __ldg(rw + 0), r1 = __ldg(rw + 1), r2 = __ldg(rw + 2), r3 = __ldg(rw + 3);
                float z = 0.f;
                z = fmaf(c0.x, r0.x, z); z = fmaf(c0.y, r0.y, z); z = fmaf(c0.z, r0.z, z); z = fmaf(c0.w, r0.w, z);
                z = fmaf(c1.x, r1.x, z); z = fmaf(c1.y, r1.y, z); z = fmaf(c1.z, r1.z, z); z = fmaf(c1.w, r1.w, z);
                z = fmaf(c2.x, r2.x, z); z = fmaf(c2.y, r2.y, z); z = fmaf(c2.z, r2.z, z); z = fmaf(c2.w, r2.w, z);
                z = fmaf(c3.x, r3.x, z); z = fmaf(c3.y, r3.y, z); z = fmaf(c3.z, r3.z, z); z = fmaf(c3.w, r3.w, z);
                s = fmaf(__ldg(&rho_bias[j]), __expf(z), s);
            }
            atomicAdd(&g_S[b], s);
        }
        return;
    }

    // ---- per-gene spline precompute + prior (warp-shuffle scans) ----
    int g = bid;
    int gene = genes_oi[g];

    float psum = 0.f;
    const float* lwr = logit_weight + (size_t)gene * (LL * CC);
    for (int i = t; i < LL * CC; i += 128) {
        float v = lwr[i];
        psum -= 0.5f * v * v;
    }
    if (t < LL) { float v = rho_weight[gene * LL + t]; psum -= 0.5f * v * v; }

    const int nh_t[3] = {128, 64, 32};
    const int oh_t[3] = {0, 128, 192};
    const int ow_t[3] = {0, 127, 190};
    const float* uhr = uh + (size_t)gene * CC;
    const float* uwr = uw + (size_t)gene * 221;

    for (int s = 0; s < 3; s++) {
        int nh = nh_t[s], nw = nh - 1, oh = oh_t[s], ow = ow_t[s];
        float uwv = (t < nw) ? uwr[ow + t] : -1e30f;

        // block max via warp reduce + 4-combine
        float m = uwv;
#pragma unroll
        for (int o = 16; o; o >>= 1) m = fmaxf(m, __shfl_xor_sync(FULL, m, o));
        if (lane == 0) s_m[wid] = m;
        __syncthreads();
        float mx = fmaxf(fmaxf(s_m[0], s_m[1]), fmaxf(s_m[2], s_m[3]));

        float e = (t < nw) ? __expf(uwv - mx) : 0.f;
        // warp sum + warp inclusive scan of e
        float sm = e;
#pragma unroll
        for (int o = 16; o; o >>= 1) sm += __shfl_xor_sync(FULL, sm, o);
        float sc = e;
#pragma unroll
        for (int o = 1; o < 32; o <<= 1) {
            float u = __shfl_up_sync(FULL, sc, o);
            if (lane >= o) sc += u;
        }
        __syncthreads();   // protect s_m before reuse of shared block
        if (lane == 0)  s_s[wid]  = sm;
        if (lane == 31) s_c[wid]  = sc;
        if (lane == 31) s_wl[wid] = e;
        __syncthreads();
        float tot = s_s[0] + s_s[1] + s_s[2] + s_s[3];
        float inv = 1.0f / tot;
        float base = 0.f;
#pragma unroll
        for (int k = 0; k < 4; k++) base += (k < wid) ? s_c[k] : 0.f;

        float inclE = sc + base;
        float prevIncl = __shfl_up_sync(FULL, inclE, 1);
        if (lane == 0) prevIncl = base;
        float prevE = __shfl_up_sync(FULL, e, 1);
        if (lane == 0) prevE = (wid > 0) ? s_wl[wid - 1] : 0.f;

        float w = e * inv;
        if (t < nh) {
            float loc = (t == 0) ? 0.f : ((t == nw) ? 1.0f : prevIncl * inv);
            float wl = (t >= 1) ? prevE * inv : 0.f;
            float wr = (t <= nw - 1) ? w : 0.f;
            float wwv = 0.5f * (wl + wr);
            float wst = (t < nw) ? w : 0.f;
            int pos;
            if (s == 0)      pos = (t & 15) * 8 + (t >> 4);
            else if (s == 1) pos = 128 + (t & 7) * 8 + (t >> 3);
            else             pos = 192 + (t & 3) * 8 + (t >> 2);
            g_spl[g * CC + pos] = make_float4(uhr[oh + t], wwv, loc, wst);
        }
        __syncthreads();   // protect smem for next split
    }

    // prior reduction (warp + 4-combine)
    float p = psum;
#pragma unroll
    for (int o = 16; o; o >>= 1) p += __shfl_xor_sync(FULL, p, o);
    if (lane == 0) s_s[wid] = p;
    __syncthreads();
    if (t == 0) atomicAdd(&g_acc[1], (double)(s_s[0] + s_s[1] + s_s[2] + s_s[3]));
}

// ======== K2: delta GEMM tf32 + smem-staged stores (R13/R15) ========
__global__ void __launch_bounds__(128) k_gemm(const int* __restrict__ genes_oi,
                                              const float* __restrict__ logit_weight,
                                              const float* __restrict__ clustering,
                                              int G) {
    __shared__ uint32_t s_lw[LL * LWP];
    __shared__ uint32_t s_out[4][16 * OSTR];
    int g = blockIdx.x, bs = blockIdx.y, t = threadIdx.x;
    int gene = __ldg(&genes_oi[g]);

    const float* lwr = logit_weight + (size_t)gene * (LL * CC);
    for (int i = t; i < LL * CC; i += 128) {
        int row = i / CC, col = i - row * CC;
        s_lw[row * LWP + col] = f2tf32(lwr[i]);
    }
    __syncthreads();

    int wid = t >> 5, lane = t & 31;
    int r = lane >> 2, k4 = lane & 3;
    uint32_t* sbuf = s_out[wid];

    for (int bt = 0; bt < 4; bt++) {
        int tilebase = (bs * 16 + wid * 4 + bt) * 16;
        int brow0 = tilebase + r;
        const float* cl0 = clustering + (size_t)brow0 * LL;
        const float* cl1 = cl0 + 8 * LL;
        uint32_t A0[4], A1[4];
        A0[0] = f2tf32(__ldg(cl0 + k4));      A0[1] = f2tf32(__ldg(cl1 + k4));
        A0[2] = f2tf32(__ldg(cl0 + k4 + 4));  A0[3] = f2tf32(__ldg(cl1 + k4 + 4));
        A1[0] = f2tf32(__ldg(cl0 + k4 + 8));  A1[1] = f2tf32(__ldg(cl1 + k4 + 8));
        A1[2] = f2tf32(__ldg(cl0 + k4 + 12)); A1[3] = f2tf32(__ldg(cl1 + k4 + 12));

#pragma unroll 4
        for (int ct = 0; ct < 28; ct++) {
            int col = (ct << 3) + r;
            uint32_t b00 = s_lw[k4 * LWP + col];
            uint32_t b01 = s_lw[(k4 + 4) * LWP + col];
            uint32_t b10 = s_lw[(k4 + 8) * LWP + col];
            uint32_t b11 = s_lw[(k4 + 12) * LWP + col];
            float d0 = 0.f, d1 = 0.f, d2 = 0.f, d3 = 0.f;
            mma_tf32(d0, d1, d2, d3, A0[0], A0[1], A0[2], A0[3], b00, b01);
            mma_tf32(d0, d1, d2, d3, A1[0], A1[1], A1[2], A1[3], b10, b11);
            sbuf[r * OSTR + (ct << 2) + k4]       = bfpack2(d0, d1);
            sbuf[(r + 8) * OSTR + (ct << 2) + k4] = bfpack2(d2, d3);
        }
        __syncwarp();
        for (int idx = lane; idx < 448; idx += 32) {
            int row = idx / 28, c4 = idx - row * 28;
            uint4 v = *(uint4*)&sbuf[row * OSTR + (c4 << 2)];
            *(uint4*)(g_d + ((size_t)(tilebase + row) * G + g) * CC + (c4 << 3)) = v;
        }
        __syncwarp();
    }
}

// ======== K3: main [0,MB) + rho [MB, MB+RB) (R15's proven k_B) ========
__global__ void __launch_bounds__(128) k_B(const float* __restrict__ coord,
                                           const int* __restrict__ lgi,
                                           const int* __restrict__ lci,
                                           const int* __restrict__ lcgi,
                                           const float* __restrict__ clustering,
                                           const float* __restrict__ rho_weight,
                                           const float* __restrict__ rho_bias,
                                           int n, int GT, int MB) {
    __shared__ double s_acc[4];
    __shared__ double sd_[128];
    const unsigned FULL = 0xffffffffu;
    int bidx = blockIdx.x, t = threadIdx.x;

    if (bidx >= MB) {
        int i = (bidx - MB) * 128 + t;
        float v = 0.f;
        if (i < n) {
            int li = __ldg(&lcgi[i]);
            int row = li / GT;
            int j = li - row * GT;
            const float4* cp = (const float4*)(clustering + (size_t)row * LL);
            const float4* rw = (const float4*)(rho_weight + (size_t)j * LL);
            float4 c0 = __ldg(cp + 0), c1 = __ldg(cp + 1), c2 = __ldg(cp + 2), c3 = __ldg(cp + 3);
            float4 r0 = __ldg(rw + 0), r1 = __ldg(rw + 1), r2 = __ldg(rw + 2), r3 = __ldg(rw + 3);
            float z = 0.f;
            z = fmaf(c0.x, r0.x, z); z = fmaf(c0.y, r0.y, z); z = fmaf(c0.z, r0.z, z); z = fmaf(c0.w, r0.w, z);
            z = fmaf(c1.x, r1.x, z); z = fmaf(c1.y, r1.y, z); z = fmaf(c1.z, r1.z, z); z = fmaf(c1.w, r1.w, z);
            z = fmaf(c2.x, r2.x, z); z = fmaf(c2.y, r2.y, z); z = fmaf(c2.z, r2.z, z); z = fmaf(c2.w, r2.w, z);
            z = fmaf(c3.x, r3.x, z); z = fmaf(c3.y, r3.y, z); z = fmaf(c3.z, r3.z, z); z = fmaf(c3.w, r3.w, z);
            v = __logf(__ldg(&rho_bias[j])) + z - __logf(__ldg(&g_S[row]));
        }
        sd_[t] = (double)v;
        __syncthreads();
        for (int o = 64; o; o >>= 1) {
            if (t < o) sd_[t] += sd_[t + o];
            __syncthreads();
        }
        if (t == 0) atomicAdd(&g_acc[0], sd_[0]);
        return;
    }

    int wid = t >> 5, lane = t & 31;
    int q = lane >> 3, ll = lane & 7;

    int cut = bidx * 16 + wid * 4 + q;
    bool live = cut < n;
    int cu = live ? cut : (n - 1);

    float x = __ldg(&coord[cu]);
    int gl = __ldg(&lgi[cu]);
    int ci = __ldg(&lci[cu]);

    const float4* splg = g_spl + (size_t)gl * CC;
    const unsigned short* drs = g_d + (size_t)ci * CC;
    const uint4* drow4 = (const uint4*)drs;
    float lad = 0.f;

    // ===== step 1 =====
    {
        uint4 u0 = __ldg(&drow4[ll * 2]);
        uint4 u1 = __ldg(&drow4[ll * 2 + 1]);
        unsigned wds[8] = {u0.x, u0.y, u0.z, u0.w, u1.x, u1.y, u1.z, u1.w};
        float dreg[16];
#pragma unroll
        for (int p = 0; p < 8; p++) { dreg[2 * p] = blo(wds[p]); dreg[2 * p + 1] = bhi(wds[p]); }
        float h[16], w[16];
        float area = 0.f; int cnt = 0;
#pragma unroll
        for (int j = 0; j < 16; j++) {
            float4 pj = __ldg(splg + (j << 3) + ll);
            float hv = __expf(pj.x + dreg[j]);
            h[j] = hv; w[j] = pj.w;
            cnt += (x >= pj.z) ? 1 : 0;
            area = fmaf(hv, pj.y, area);
        }
        cnt += __shfl_xor_sync(FULL, cnt, 1, 8);
        cnt += __shfl_xor_sync(FULL, cnt, 2, 8);
        cnt += __shfl_xor_sync(FULL, cnt, 4, 8);
        int bin = iminmax(cnt - 1, 126);
        float wprev = __shfl_up_sync(FULL, w[15], 1, 8);
        float cdf = 0.f;
        int ib = ll << 4;
        float wim1 = wprev;
#pragma unroll
        for (int j = 0; j < 16; j++) {
            int i = ib + j;
            float ct = ((i < bin) ? 0.5f * w[j] : 0.f) + ((i >= 1 && i <= bin) ? 0.5f * wim1 : 0.f);
            cdf = fmaf(h[j], ct, cdf);
            wim1 = w[j];
        }
        area += __shfl_xor_sync(FULL, area, 4, 8);
        cdf  += __shfl_xor_sync(FULL, cdf, 4, 8);
        float v = (lane & 4) ? cdf : area;
        v += __shfl_xor_sync(FULL, v, 1, 8);
        v += __shfl_xor_sync(FULL, v, 2, 8);
        float o = __shfl_xor_sync(FULL, v, 4, 8);
        area = (lane & 4) ? o : v;
        cdf  = (lane & 4) ? v : o;

        int b1 = bin + 1;
        float4 spb  = __ldg(splg + ((bin & 15) << 3) + (bin >> 4));
        float4 spb1 = __ldg(splg + ((b1 & 15) << 3) + (b1 >> 4));
        float hl = __expf(spb.x + dsc(drs, bin));
        float hr = __expf(spb1.x + dsc(drs, b1));
        float inv = __fdividef(1.f, area);
        float alpha = __fdividef(x - spb.z, spb.w);
        float hln = hl * inv, hrn = hr * inv;
        x = (0.5f * (hrn - hln) * alpha + hln) * spb.w * alpha + cdf * inv;
        lad += __logf(fmaf(hrn - hln, alpha, hln));
    }

    // ===== step 2 =====
    {
        uint4 u0 = __ldg(&drow4[16 + ll]);
        unsigned wds[4] = {u0.x, u0.y, u0.z, u0.w};
        float dreg[8];
#pragma unroll
        for (int p = 0; p < 4; p++) { dreg[2 * p] = blo(wds[p]); dreg[2 * p + 1] = bhi(wds[p]); }
        float h[8], w[8];
        float area = 0.f; int cnt = 0;
#pragma unroll
        for (int j = 0; j < 8; j++) {
            float4 pj = __ldg(splg + 128 + (j << 3) + ll);
            float hv = __expf(pj.x + dreg[j]);
            h[j] = hv; w[j] = pj.w;
            cnt += (x >= pj.z) ? 1 : 0;
            area = fmaf(hv, pj.y, area);
        }
        cnt += __shfl_xor_sync(FULL, cnt, 1, 8);
        cnt += __shfl_xor_sync(FULL, cnt, 2, 8);
        cnt += __shfl_xor_sync(FULL, cnt, 4, 8);
        int bin = iminmax(cnt - 1, 62);
        float wprev = __shfl_up_sync(FULL, w[7], 1, 8);
        float cdf = 0.f;
        int ib = ll << 3;
        float wim1 = wprev;
#pragma unroll
        for (int j = 0; j < 8; j++) {
            int i = ib + j;
            float ct = ((i < bin) ? 0.5f * w[j] : 0.f) + ((i >= 1 && i <= bin) ? 0.5f * wim1 : 0.f);
            cdf = fmaf(h[j], ct, cdf);
            wim1 = w[j];
        }
        area += __shfl_xor_sync(FULL, area, 4, 8);
        cdf  += __shfl_xor_sync(FULL, cdf, 4, 8);
        float v = (lane & 4) ? cdf : area;
        v += __shfl_xor_sync(FULL, v, 1, 8);
        v += __shfl_xor_sync(FULL, v, 2, 8);
        float o = __shfl_xor_sync(FULL, v, 4, 8);
        area = (lane & 4) ? o : v;
        cdf  = (lane & 4) ? v : o;

        int b1 = bin + 1;
        float4 spb  = __ldg(splg + 128 + ((bin & 7) << 3) + (bin >> 3));
        float4 spb1 = __ldg(splg + 128 + ((b1 & 7) << 3) + (b1 >> 3));
        float hl = __expf(spb.x + dsc(drs, 128 + bin));
        float hr = __expf(spb1.x + dsc(drs, 128 + b1));
        float inv = __fdividef(1.f, area);
        float alpha = __fdividef(x - spb.z, spb.w);
        float hln = hl * inv, hrn = hr * inv;
        x = (0.5f * (hrn - hln) * alpha + hln) * spb.w * alpha + cdf * inv;
        lad += __logf(fmaf(hrn - hln, alpha, hln));
    }

    // ===== step 3 =====
    {
        uint2 u0 = __ldg(&((const uint2*)drow4)[48 + ll]);
        float dreg[4] = {blo(u0.x), bhi(u0.x), blo(u0.y), bhi(u0.y)};
        float h[4], w[4];
        float area = 0.f; int cnt = 0;
#pragma unroll
        for (int j = 0; j < 4; j++) {
            float4 pj = __ldg(splg + 192 + (j << 3) + ll);
            float hv = __expf(pj.x + dreg[j]);
            h[j] = hv; w[j] = pj.w;
            cnt += (x >= pj.z) ? 1 : 0;
            area = fmaf(hv, pj.y, area);
        }
        cnt += __shfl_xor_sync(FULL, cnt, 1, 8);
        cnt += __shfl_xor_sync(FULL, cnt, 2, 8);
        cnt += __shfl_xor_sync(FULL, cnt, 4, 8);
        int bin = iminmax(cnt - 1, 30);
        float wprev = __shfl_up_sync(FULL, w[3], 1, 8);
        float cdf = 0.f;
        int ib = ll << 2;
        float wim1 = wprev;
#pragma unroll
        for (int j = 0; j < 4; j++) {
            int i = ib + j;
            float ct = ((i < bin) ? 0.5f * w[j] : 0.f) + ((i >= 1 && i <= bin) ? 0.5f * wim1 : 0.f);
            cdf = fmaf(h[j], ct, cdf);
            wim1 = w[j];
        }
        area += __shfl_xor_sync(FULL, area, 4, 8);
        cdf  += __shfl_xor_sync(FULL, cdf, 4, 8);
        float v = (lane & 4) ? cdf : area;
        v += __shfl_xor_sync(FULL, v, 1, 8);
        v += __shfl_xor_sync(FULL, v, 2, 8);
        float o = __shfl_xor_sync(FULL, v, 4, 8);
        area = (lane & 4) ? o : v;
        cdf  = (lane & 4) ? v : o;

        int b1 = bin + 1;
        float4 spb  = __ldg(splg + 192 + ((bin & 3) << 3) + (bin >> 2));
        float4 spb1 = __ldg(splg + 192 + ((b1 & 3) << 3) + (b1 >> 2));
        float hl = __expf(spb.x + dsc(drs, 192 + bin));
        float hr = __expf(spb1.x + dsc(drs, 192 + b1));
        float inv = __fdividef(1.f, area);
        float alpha = __fdividef(x - spb.z, spb.w);
        float hln = hl * inv, hrn = hr * inv;
        x = (0.5f * (hrn - hln) * alpha + hln) * spb.w * alpha + cdf * inv;
        lad += __logf(fmaf(hrn - hln, alpha, hln));
    }

    double acc = (live && ll == 0) ? (double)lad : 0.0;
    acc += __shfl_xor_sync(FULL, acc, 8);
    acc += __shfl_xor_sync(FULL, acc, 16);
    if (lane == 0) s_acc[wid] = acc;
    __syncthreads();
    if (t == 0) {
        double tt = s_acc[0] + s_acc[1] + s_acc[2] + s_acc[3];
        atomicAdd(&g_acc[0], tt);
    }
}

// ---------------- K4: finalize + restore ----------------
__global__ void k_final(float* out, int G, int N, float logGT) {
    int t = threadIdx.x;
    if (t == 0) {
        double cnt = (double)G * (double)(LL * CC + LL);
        out[0] = (float)(-g_acc[0] - (double)N * (double)logGT
                         - g_acc[1] + 0.5 * LOG2PI * cnt);
    }
    __syncthreads();
    if (t < BB) g_S[t] = 0.f;
    if (t < 2) g_acc[t] = 0.0;
}

// ---------------- launch ----------------
extern "C" void kernel_launch(void* const* d_in, const int* in_sizes, int n_in,
                              void* d_out, int out_size) {
    const float* clustering    = (const float*)d_in[0];
    const float* coordinates   = (const float*)d_in[1];
    const int*   genes_oi      = (const int*)d_in[2];
    const int*   local_gene_ix = (const int*)d_in[3];
    const int*   lci           = (const int*)d_in[4];
    const int*   lcgi          = (const int*)d_in[5];
    const float* logit_weight  = (const float*)d_in[6];
    const float* rho_weight    = (const float*)d_in[7];
    const float* rho_bias      = (const float*)d_in[8];
    const float* uh            = (const float*)d_in[9];
    const float* uw            = (const float*)d_in[10];

    int N  = in_sizes[1];
    int G  = in_sizes[2];
    int B  = in_sizes[0] / LL;
    int GT = in_sizes[8];

    int SB = (GT + JPB - 1) / JPB;       // 313
    int MB = (N + 15) / 16;              // 12500
    int RB = (N + 127) / 128;            // 1563

    k_preS<<<G + SB, 128>>>(genes_oi, logit_weight, rho_weight, rho_bias,
                            uh, uw, clustering, G, GT);
    k_gemm<<<dim3(G, B / 256), 128>>>(genes_oi, logit_weight, clustering, G);
    k_B<<<MB + RB, 128>>>(coordinates, local_gene_ix, lci, lcgi,
                          clustering, rho_weight, rho_bias, N, GT, MB);
    k_final<<<1, 512>>>((float*)d_out, G, N, logf((float)GT));
}